// round 6
// baseline (speedup 1.0000x reference)
#include <cuda_runtime.h>

#define DD 8
#define BB 4096
#define VV 1024
#define K_SEL 102
#define THREADS 256
#define RPC 2                       // rows per CTA

__device__ int g_samples[DD * BB];

__device__ __forceinline__ unsigned fkey(float f) {
    unsigned b = __float_as_uint(f);
    return (b & 0x80000000u) ? ~b : (b | 0x80000000u);
}
__device__ __forceinline__ float keyf(unsigned k) {
    unsigned b = (k & 0x80000000u) ? (k & 0x7FFFFFFFu) : ~k;
    return __uint_as_float(b);
}

__global__ __launch_bounds__(THREADS)
void decode_kernel(const float* __restrict__ logits,
                   const float* __restrict__ uin,
                   const int* __restrict__ curv,
                   float* __restrict__ out_probs,
                   int write_probs)
{
    const int r0   = blockIdx.x * RPC;
    const int tid  = threadIdx.x;
    const int lane = tid & 31;
    const int wid  = tid >> 5;
    const float NEG = __int_as_float(0xff800000);
    const unsigned FULL = 0xffffffffu;
    const int vbase = tid * 4;

    __shared__ int sh_hist[256];               // packed: row0 lo16, row1 hi16
    __shared__ int sh_wsum[8];
    __shared__ unsigned sh_sel[RPC];
    __shared__ int sh_krem[RPC];
    __shared__ int sh_cnt[RPC];
    __shared__ unsigned sh_maxkey[RPC];
    __shared__ unsigned long long sh_best[RPC];
    __shared__ float sh_red[RPC][8];
    __shared__ float sh_logZ[RPC];

    sh_hist[tid] = 0;
    if (tid < RPC) { sh_maxkey[tid] = 0u; sh_best[tid] = 0ull; }

    // ---- front-load both rows (MLP=2), mask, keys ----
    float vals[RPC][4];
    unsigned keys[RPC][4];
    size_t base[RPC];
#pragma unroll
    for (int q = 0; q < RPC; ++q) {
        base[q] = (size_t)(r0 + q) * VV;
        float4 lv = ((const float4*)(logits + base[q]))[tid];
        vals[q][0] = lv.x; vals[q][1] = lv.y; vals[q][2] = lv.z; vals[q][3] = lv.w;
        int cur = curv[r0 + q];
#pragma unroll
        for (int j = 0; j < 4; ++j) {
            int v = vbase + j;
            if (v < cur || v == 0) vals[q][j] = NEG;
            keys[q][j] = fkey(vals[q][j]);
        }
    }

    // per-warp butterfly max for both rows
    unsigned lmax[RPC];
#pragma unroll
    for (int q = 0; q < RPC; ++q) {
        unsigned mk = max(max(keys[q][0], keys[q][1]), max(keys[q][2], keys[q][3]));
#pragma unroll
        for (int off = 16; off >= 1; off >>= 1)
            mk = max(mk, __shfl_xor_sync(FULL, mk, off));
        lmax[q] = mk;
    }

    __syncthreads();                            // fence init (hist zero, maxkey=0)
    if (lane == 0) {
#pragma unroll
        for (int q = 0; q < RPC; ++q) atomicMax(&sh_maxkey[q], lmax[q]);
    }

    // ---- dual-row exact radix select (packed histogram) ----
    unsigned prefix[RPC] = {0u, 0u};
    int krem[RPC] = {K_SEL, K_SEL};
    bool done[RPC] = {false, false};
    unsigned pmask = 0u;
    for (int pass = 0; pass < 4; ++pass) {
        const int shift = 24 - 8 * pass;
#pragma unroll
        for (int q = 0; q < RPC; ++q) {
            if (done[q]) continue;
            const int inc = 1 << (16 * q);
#pragma unroll
            for (int j = 0; j < 4; ++j)
                if ((keys[q][j] & pmask) == prefix[q])
                    atomicAdd(&sh_hist[(keys[q][j] >> shift) & 0xFFu], inc);
        }
        __syncthreads();
        int cntp = sh_hist[tid];
        sh_hist[tid] = 0;                       // self-reset for next pass
        int x = cntp;                           // packed suffix scan (no carry: each half <= 1024)
#pragma unroll
        for (int off = 1; off < 32; off <<= 1) {
            int y = __shfl_down_sync(FULL, x, off);
            if (lane + off < 32) x += y;
        }
        if (lane == 0) sh_wsum[wid] = x;
        __syncthreads();
        int tail = 0;
#pragma unroll
        for (int w = 1; w < 8; ++w)
            if (w > wid) tail += sh_wsum[w];
        int sufp = x + tail;
#pragma unroll
        for (int q = 0; q < RPC; ++q) {
            if (done[q]) continue;
            int suf = (sufp >> (16 * q)) & 0xFFFF;
            int c   = (cntp >> (16 * q)) & 0xFFFF;
            if (suf >= krem[q] && (suf - c) < krem[q]) {
                sh_sel[q]  = (unsigned)tid;
                sh_krem[q] = krem[q] - (suf - c);
                sh_cnt[q]  = c;
            }
        }
        __syncthreads();
        bool alldone = true;
#pragma unroll
        for (int q = 0; q < RPC; ++q) {
            if (!done[q]) {
                prefix[q] |= sh_sel[q] << shift;
                krem[q]    = sh_krem[q];
                if (sh_cnt[q] == krem[q]) done[q] = true;   // whole bucket kept: exact
            }
            alldone &= done[q];
        }
        pmask |= 0xFFu << shift;
        if (alldone) break;
        __syncthreads();                        // fence self-reset & sel reuse
    }
    // kept := key >= prefix[q]  (exact threshold or exact bucket floor)

    // ---- softmax normalizers for both rows ----
    float m[RPC];
#pragma unroll
    for (int q = 0; q < RPC; ++q) m[q] = keyf(sh_maxkey[q]);   // fenced above

#pragma unroll
    for (int q = 0; q < RPC; ++q) {
        float s = 0.f;
#pragma unroll
        for (int j = 0; j < 4; ++j)
            if (keys[q][j] >= prefix[q]) s += __expf(vals[q][j] - m[q]);
#pragma unroll
        for (int off = 16; off >= 1; off >>= 1)
            s += __shfl_down_sync(FULL, s, off);
        if (lane == 0) sh_red[q][wid] = s;
    }
    __syncthreads();
    if (tid < RPC) {
        float t = 0.f;
#pragma unroll
        for (int w = 0; w < 8; ++w) t += sh_red[tid][w];
        sh_logZ[tid] = m[tid] + __logf(t);
    }
    __syncthreads();

    // ---- probs + Gumbel argmax per row; u loaded only for kept ----
#pragma unroll
    for (int q = 0; q < RPC; ++q) {
        const float logZ = sh_logZ[q];
        float p[4];
        bool kept[4];
#pragma unroll
        for (int j = 0; j < 4; ++j) {
            kept[j] = (keys[q][j] >= prefix[q]);
            p[j] = kept[j] ? __expf(vals[q][j] - logZ) : 0.f;
        }
        unsigned long long best = 0ull;
        bool anyk = kept[0] | kept[1] | kept[2] | kept[3];
        if (__ballot_sync(FULL, anyk)) {
#pragma unroll
            for (int j = 0; j < 4; ++j) {
                if (kept[j]) {
                    int idx = vbase + j;
                    float u  = __ldg(uin + base[q] + idx);
                    float g  = -__logf(-__logf(u + 1e-20f) + 1e-20f);
                    float sc = (vals[q][j] - logZ) + g;   // same expr as reference
                    unsigned long long k64 =
                        ((unsigned long long)fkey(sc) << 32) |
                        (unsigned long long)(0xFFFFFFFFu - (unsigned)idx);
                    if (k64 > best) best = k64;
                }
            }
        }
        if (best) atomicMax(&sh_best[q], best);
        if (write_probs)
            ((float4*)(out_probs + base[q]))[tid] = make_float4(p[0], p[1], p[2], p[3]);
    }
    __syncthreads();
    if (tid < RPC)
        g_samples[r0 + tid] =
            (int)(0xFFFFFFFFu - (unsigned)(sh_best[tid] & 0xFFFFFFFFull));
}

__global__ void tokens_kernel(float* __restrict__ out_tok)
{
    int i = blockIdx.x * blockDim.x + threadIdx.x;   // i in [0, B*D)
    if (i >= BB * DD) return;
    int b = i / DD, d = i % DD;
    int s0 = g_samples[b];
    int sd = g_samples[d * BB + b];
    int val = (d == 0 || s0 == 1) ? sd : 0;          // NOTE_TYPE == 1
    out_tok[i] = (float)val;                         // tokens.T flattened [B,D]
}

extern "C" void kernel_launch(void* const* d_in, const int* in_sizes, int n_in,
                              void* d_out, int out_size)
{
    const float* logits = (const float*)d_in[0];
    const float* uin    = (const float*)d_in[1];
    const int*   curv   = (const int*)d_in[2];
    float* out = (float*)d_out;

    const size_t probsN = (size_t)DD * BB * VV;
    const size_t tokN   = (size_t)BB * DD;

    float* out_tok = nullptr;
    float* out_probs = nullptr;
    if ((size_t)out_size >= probsN + tokN) {        // concat: tokens.T then probs
        out_tok = out; out_probs = out + tokN;
    } else if ((size_t)out_size >= probsN) {        // probs only
        out_probs = out;
    } else {                                        // tokens only
        out_tok = out;
    }

    decode_kernel<<<(DD * BB) / RPC, THREADS>>>(logits, uin, curv,
                                                out_probs ? out_probs : out,
                                                out_probs != nullptr ? 1 : 0);
    if (out_tok)
        tokens_kernel<<<(BB * DD + 255) / 256, 256>>>(out_tok);
}